// round 3
// baseline (speedup 1.0000x reference)
#include <cuda_runtime.h>
#include <float.h>

// Problem constants
#define BB   64
#define DD   64
#define TTm  4096
#define KKm  512
#define TILE 128      // tokens per CTA
#define KCH  128      // codes per chunk
#define ESP  132      // padded smem stride for transposed emb chunk
#define NTH  256

#define N_ELEM ((size_t)BB * DD * TTm)   // 16777216

// dynamic smem (floats): zs + es + c2s + x2s + rd + rk + kidx + wred
#define SMEM_FLOATS (DD*TILE + DD*ESP + KCH + TILE + TILE*17 + TILE*17 + TILE + NTH/32)
#define SMEM_BYTES  (SMEM_FLOATS * 4)

__device__ double g_loss;
__device__ float  g_c2[KKm];

__device__ __forceinline__ unsigned long long pk2(float lo, float hi) {
    unsigned long long r;
    asm("mov.b64 %0, {%1, %2};" : "=l"(r) : "f"(lo), "f"(hi));
    return r;
}
__device__ __forceinline__ void fma2(unsigned long long &acc,
                                     unsigned long long a,
                                     unsigned long long b) {
    asm("fma.rn.f32x2 %0, %1, %2, %3;" : "=l"(acc) : "l"(a), "l"(b), "l"(acc));
}
__device__ __forceinline__ void upk2(unsigned long long v, float &lo, float &hi) {
    asm("mov.b64 {%0, %1}, %2;" : "=f"(lo), "=f"(hi) : "l"(v));
}

// ---------------------------------------------------------------------------
// prep: codebook squared norms (rounded squares + pairwise tree sum, XLA-style)
//       + zero the loss accumulator. Runs every launch (graph-safe).
// ---------------------------------------------------------------------------
__global__ void vq_prep(const float* __restrict__ emb) {
    int k = threadIdx.x;
    if (k == 0) g_loss = 0.0;
    if (k < KKm) {
        const float* e = emb + k * DD;
        float p[DD];
        #pragma unroll
        for (int d = 0; d < DD; d++) {
            float v = e[d];
            p[d] = __fmul_rn(v, v);          // rounded square (matches emb*emb)
        }
        #pragma unroll
        for (int w = DD; w > 1; w >>= 1) {   // balanced adjacent-pair tree
            #pragma unroll
            for (int i = 0; i < DD / 2; i++) {
                if (i < w / 2) p[i] = __fadd_rn(p[2 * i], p[2 * i + 1]);
            }
        }
        g_c2[k] = p[0];
    }
}

// ---------------------------------------------------------------------------
// main: fused distance GEMM + argmin + gather + straight-through + loss sum
// Distances replicate the reference's rounding exactly:
//   d = fl( fl(x2 + c2) - fl(2 * dot) ), dot = ascending-k fp32 fma chain.
// ---------------------------------------------------------------------------
__global__ __launch_bounds__(NTH, 1)
void vq_main(const float* __restrict__ z, const float* __restrict__ emb,
             float* __restrict__ out) {
    extern __shared__ float smem[];
    float* zs   = smem;                       // 64*128
    float* es   = zs + DD * TILE;             // 64*132
    float* c2s  = es + DD * ESP;              // 128
    float* x2s  = c2s + KCH;                  // 128 (per-token ||x||^2)
    float* rd   = x2s + TILE;                 // 128*17
    int*   rk   = (int*)(rd + TILE * 17);     // 128*17
    int*   kidx = rk + TILE * 17;             // 128
    float* wred = (float*)(kidx + TILE);      // 8

    const int tid = threadIdx.x;
    const int tx  = tid & 15;       // code-column group (8 codes)
    const int ty  = tid >> 4;       // token-row group (8 tokens)
    const int tile = blockIdx.x;
    const int b    = tile >> 5;
    const int t0   = (tile & 31) * TILE;
    const size_t zbase = (size_t)b * DD * TTm + t0;

    // ---- load z tile [64 dims x 128 tokens], coalesced float4 ----
    for (int i = tid; i < DD * TILE / 4; i += NTH) {
        int row = i >> 5;
        int col = (i & 31) << 2;
        float4 v = *(const float4*)(z + zbase + (size_t)row * TTm + col);
        *(float4*)(zs + row * TILE + col) = v;
    }
    __syncthreads();

    // ---- per-token ||x||^2 (ascending-d fma chain; exact order is argmin-
    // invariant: x2 enters as a constant shift of all 512 distances) ----
    if (tid < TILE) {
        float s = 0.f;
        #pragma unroll
        for (int d = 0; d < DD; d++) {
            float v = zs[d * TILE + tid];
            s = fmaf(v, v, s);
        }
        x2s[tid] = s;
    }

    float bestd[8];
    int   bestk[8];
    #pragma unroll
    for (int i = 0; i < 8; i++) { bestd[i] = FLT_MAX; bestk[i] = 0; }

    #pragma unroll 1
    for (int c = 0; c < KKm / KCH; c++) {
        __syncthreads();   // prev chunk compute done; also publishes x2s on c=0
        // load emb chunk transposed: es[d][kk] = emb[c*128+kk][d]
        for (int i = tid; i < KCH * DD / 4; i += NTH) {
            int kk = i >> 4;
            int dq = (i & 15) << 2;
            float4 v = *(const float4*)(emb + (size_t)(c * KCH + kk) * DD + dq);
            es[(dq + 0) * ESP + kk] = v.x;
            es[(dq + 1) * ESP + kk] = v.y;
            es[(dq + 2) * ESP + kk] = v.z;
            es[(dq + 3) * ESP + kk] = v.w;
        }
        if (tid < KCH) c2s[tid] = g_c2[c * KCH + tid];
        __syncthreads();

        unsigned long long acc[4][8];
        #pragma unroll
        for (int m = 0; m < 4; m++)
            #pragma unroll
            for (int j = 0; j < 8; j++) acc[m][j] = 0ull;

        // ascending-k fp32 fma chains (per lane) — matches sgemm numerics
        #pragma unroll 8
        for (int d = 0; d < DD; d++) {
            float4 a0 = *(const float4*)(zs + d * TILE + ty * 8);
            float4 a1 = *(const float4*)(zs + d * TILE + ty * 8 + 4);
            float4 b0 = *(const float4*)(es + d * ESP + tx * 8);
            float4 b1 = *(const float4*)(es + d * ESP + tx * 8 + 4);
            unsigned long long a2[4];
            a2[0] = pk2(a0.x, a0.y);
            a2[1] = pk2(a0.z, a0.w);
            a2[2] = pk2(a1.x, a1.y);
            a2[3] = pk2(a1.z, a1.w);
            float bv[8] = {b0.x, b0.y, b0.z, b0.w, b1.x, b1.y, b1.z, b1.w};
            #pragma unroll
            for (int j = 0; j < 8; j++) {
                unsigned long long b2 = pk2(bv[j], bv[j]);
                #pragma unroll
                for (int m = 0; m < 4; m++) fma2(acc[m][j], a2[m], b2);
            }
        }

        // chunk epilogue: d = fl( fl(x2 + c2) - fl(2*dot) ) — reference rounding
        #pragma unroll
        for (int j = 0; j < 8; j++) {
            float c2v = c2s[tx * 8 + j];
            int   kg  = c * KCH + tx * 8 + j;
            #pragma unroll
            for (int m = 0; m < 4; m++) {
                float lo, hi;
                upk2(acc[m][j], lo, hi);
                int tok0 = ty * 8 + 2 * m;
                float A0 = __fadd_rn(x2s[tok0],     c2v);
                float A1 = __fadd_rn(x2s[tok0 + 1], c2v);
                float d0 = __fsub_rn(A0, __fmul_rn(2.0f, lo));
                float d1 = __fsub_rn(A1, __fmul_rn(2.0f, hi));
                if (d0 < bestd[2 * m])     { bestd[2 * m]     = d0; bestk[2 * m]     = kg; }
                if (d1 < bestd[2 * m + 1]) { bestd[2 * m + 1] = d1; bestk[2 * m + 1] = kg; }
            }
        }
    }

    // ---- cross-thread argmin reduce (16 code-groups per token) ----
    #pragma unroll
    for (int i = 0; i < 8; i++) {
        int tok = ty * 8 + i;
        rd[tok * 17 + tx] = bestd[i];
        rk[tok * 17 + tx] = bestk[i];
    }
    __syncthreads();
    if (tid < TILE) {
        float bd = rd[tid * 17];
        int   bk = rk[tid * 17];
        #pragma unroll
        for (int x = 1; x < 16; x++) {
            float dv = rd[tid * 17 + x];
            int   kv = rk[tid * 17 + x];
            if (dv < bd || (dv == bd && kv < bk)) { bd = dv; bk = kv; }
        }
        kidx[tid] = bk;
    }
    __syncthreads();

    // ---- gather + straight-through output + squared-error partial sum ----
    // Replicate reference rounding: out = z + (q - z).
    float lsum = 0.f;
    for (int i = tid; i < DD * TILE; i += NTH) {
        int d = i >> 7;
        int t = i & 127;
        float q  = __ldg(emb + kidx[t] * DD + d);
        float zv = zs[d * TILE + t];
        float diff = __fsub_rn(q, zv);
        out[zbase + (size_t)d * TTm + t] = __fadd_rn(zv, diff);
        lsum = fmaf(diff, diff, lsum);
    }
    #pragma unroll
    for (int o = 16; o > 0; o >>= 1)
        lsum += __shfl_down_sync(0xffffffffu, lsum, o);
    if ((tid & 31) == 0) wred[tid >> 5] = lsum;
    __syncthreads();
    if (tid == 0) {
        float s = 0.f;
        #pragma unroll
        for (int w = 0; w < NTH / 32; w++) s += wred[w];
        atomicAdd(&g_loss, (double)s);
    }
}

// ---------------------------------------------------------------------------
// finalize: write the two loss scalars
// ---------------------------------------------------------------------------
__global__ void vq_fin(float* __restrict__ out) {
    double m = g_loss / (double)N_ELEM;
    out[N_ELEM]     = (float)m;           // vq_loss = mean((q - z)^2)
    out[N_ELEM + 1] = (float)(0.25 * m);  // commitment = 0.25 * same mean
}

// ---------------------------------------------------------------------------
extern "C" void kernel_launch(void* const* d_in, const int* in_sizes, int n_in,
                              void* d_out, int out_size) {
    const float* z   = (const float*)d_in[0];
    const float* emb = (const float*)d_in[1];
    float*       out = (float*)d_out;

    (void)cudaFuncSetAttribute(vq_main,
                               cudaFuncAttributeMaxDynamicSharedMemorySize,
                               SMEM_BYTES);

    vq_prep<<<1, 512>>>(emb);
    vq_main<<<(BB * TTm) / TILE, NTH, SMEM_BYTES>>>(z, emb, out);
    vq_fin<<<1, 1>>>(out);
}